// round 1
// baseline (speedup 1.0000x reference)
#include <cuda_runtime.h>

#define N_TOKENS 8192
#define IN_CH    4096
#define OUT_CH   4096
#define RANK     16

typedef unsigned long long u64;

// scratch for t = x @ R^T : [8192, 16] fp32  (device global — no allocation)
__device__ float g_t[N_TOKENS * RANK];

__device__ __forceinline__ u64 f2fma(u64 a, u64 b, u64 c) {
    u64 d;
    asm("fma.rn.f32x2 %0, %1, %2, %3;" : "=l"(d) : "l"(a), "l"(b), "l"(c));
    return d;
}

__device__ __forceinline__ u64 splat2(float v) {
    u64 d;
    asm("mov.b64 %0, {%1, %1};" : "=l"(d) : "f"(v));
    return d;
}

// ----------------------------------------------------------------------------
// Kernel 1: t[n, r] = sum_k x[n,k] * R[r,k]
// 256 blocks x 256 threads; each warp owns 4 tokens, lanes stride over k.
// R rows hoisted across the 4 tokens (16 R loads amortized over 128 FFMA2).
// ----------------------------------------------------------------------------
__global__ void __launch_bounds__(256, 1)
k1_xRt(const float* __restrict__ x, const float* __restrict__ Rm) {
    const int warp = threadIdx.x >> 5;
    const int lane = threadIdx.x & 31;
    const int tok0 = blockIdx.x * 32 + warp * 4;

    u64 acc[4][16];
#pragma unroll
    for (int tk = 0; tk < 4; tk++)
#pragma unroll
        for (int r = 0; r < 16; r++) acc[tk][r] = 0ull;   // bits of (0.f, 0.f)

    const ulonglong2* x0 = reinterpret_cast<const ulonglong2*>(x + (size_t)(tok0 + 0) * IN_CH) + lane;
    const ulonglong2* x1 = reinterpret_cast<const ulonglong2*>(x + (size_t)(tok0 + 1) * IN_CH) + lane;
    const ulonglong2* x2 = reinterpret_cast<const ulonglong2*>(x + (size_t)(tok0 + 2) * IN_CH) + lane;
    const ulonglong2* x3 = reinterpret_cast<const ulonglong2*>(x + (size_t)(tok0 + 3) * IN_CH) + lane;
    const ulonglong2* Rp = reinterpret_cast<const ulonglong2*>(Rm) + lane;

#pragma unroll 1
    for (int i = 0; i < 32; i++) {
        const int off = i * 32;   // ull2 units; lane already folded into base
        ulonglong2 xv0 = x0[off];
        ulonglong2 xv1 = x1[off];
        ulonglong2 xv2 = x2[off];
        ulonglong2 xv3 = x3[off];
#pragma unroll
        for (int r = 0; r < 16; r++) {
            ulonglong2 rv = Rp[r * (IN_CH / 4) + off];
            acc[0][r] = f2fma(xv0.x, rv.x, acc[0][r]);
            acc[0][r] = f2fma(xv0.y, rv.y, acc[0][r]);
            acc[1][r] = f2fma(xv1.x, rv.x, acc[1][r]);
            acc[1][r] = f2fma(xv1.y, rv.y, acc[1][r]);
            acc[2][r] = f2fma(xv2.x, rv.x, acc[2][r]);
            acc[2][r] = f2fma(xv2.y, rv.y, acc[2][r]);
            acc[3][r] = f2fma(xv3.x, rv.x, acc[3][r]);
            acc[3][r] = f2fma(xv3.y, rv.y, acc[3][r]);
        }
    }

    // cross-lane reduction, then lane 0 writes the 16-float t row
#pragma unroll
    for (int tk = 0; tk < 4; tk++) {
        float s[16];
#pragma unroll
        for (int r = 0; r < 16; r++) {
            float2 v = *reinterpret_cast<float2*>(&acc[tk][r]);
            s[r] = v.x + v.y;
        }
#pragma unroll
        for (int off = 16; off > 0; off >>= 1) {
#pragma unroll
            for (int r = 0; r < 16; r++)
                s[r] += __shfl_xor_sync(0xffffffffu, s[r], off);
        }
        if (lane == 0) {
            float4* o = reinterpret_cast<float4*>(g_t + (size_t)(tok0 + tk) * RANK);
            o[0] = make_float4(s[0],  s[1],  s[2],  s[3]);
            o[1] = make_float4(s[4],  s[5],  s[6],  s[7]);
            o[2] = make_float4(s[8],  s[9],  s[10], s[11]);
            o[3] = make_float4(s[12], s[13], s[14], s[15]);
        }
    }
}

// ----------------------------------------------------------------------------
// Kernel 2: out[n, o] = bias[o] + sum_r t[n,r] * L[o,r]
// Tile: 32 tokens x 512 outputs per block (128 threads, 4 consecutive o each).
// L chunk transposed into smem (LDS.128), t pre-splatted as f32x2 pairs,
// L register value reused across 8-token blocks.
// ----------------------------------------------------------------------------
__global__ void __launch_bounds__(128)
k2_tLt(const float* __restrict__ Lm, const float* __restrict__ bias,
       float* __restrict__ out) {
    __shared__ __align__(16) float Lt[16][512];     // Lt[r][o_local]
    __shared__ __align__(16) u64   ts2[32][16];     // splatted t[tok][r]

    const int tid = threadIdx.x;
    const int bt = blockIdx.x >> 3;     // token tile 0..255
    const int bo = blockIdx.x & 7;      // o chunk 0..7
    const int obase   = bo * 512;
    const int tokbase = bt * 32;

    // stage L chunk transposed: 512 rows of 16 floats
#pragma unroll
    for (int j = 0; j < 4; j++) {
        const int ol = tid + 128 * j;
        const float4* lr = reinterpret_cast<const float4*>(Lm + (size_t)(obase + ol) * RANK);
        float4 a = lr[0], b = lr[1], c = lr[2], d = lr[3];
        Lt[0][ol]  = a.x; Lt[1][ol]  = a.y; Lt[2][ol]  = a.z; Lt[3][ol]  = a.w;
        Lt[4][ol]  = b.x; Lt[5][ol]  = b.y; Lt[6][ol]  = b.z; Lt[7][ol]  = b.w;
        Lt[8][ol]  = c.x; Lt[9][ol]  = c.y; Lt[10][ol] = c.z; Lt[11][ol] = c.w;
        Lt[12][ol] = d.x; Lt[13][ol] = d.y; Lt[14][ol] = d.z; Lt[15][ol] = d.w;
    }

    // stage t rows, pre-splatted to f32x2 (both halves = t value)
    {
        const float4* tp = reinterpret_cast<const float4*>(g_t + (size_t)tokbase * RANK);
        float4 v = tp[tid];                 // 128 threads * 4 = 512 floats = 32x16
        const int tok = tid >> 2;
        const int r0  = (tid & 3) * 4;
        ts2[tok][r0 + 0] = splat2(v.x);
        ts2[tok][r0 + 1] = splat2(v.y);
        ts2[tok][r0 + 2] = splat2(v.z);
        ts2[tok][r0 + 3] = splat2(v.w);
    }

    const ulonglong2 bv = *reinterpret_cast<const ulonglong2*>(bias + obase + tid * 4);
    __syncthreads();

    const int o4 = tid * 4;
#pragma unroll 1
    for (int tb = 0; tb < 4; tb++) {
        u64 accA[8], accB[8];
#pragma unroll
        for (int tk = 0; tk < 8; tk++) { accA[tk] = bv.x; accB[tk] = bv.y; }

#pragma unroll
        for (int r = 0; r < 16; r++) {
            ulonglong2 Lv = *reinterpret_cast<const ulonglong2*>(&Lt[r][o4]);
#pragma unroll
            for (int tk = 0; tk < 8; tk++) {
                u64 t2 = ts2[tb * 8 + tk][r];
                accA[tk] = f2fma(t2, Lv.x, accA[tk]);
                accB[tk] = f2fma(t2, Lv.y, accB[tk]);
            }
        }

#pragma unroll
        for (int tk = 0; tk < 8; tk++) {
            ulonglong2 o;
            o.x = accA[tk];
            o.y = accB[tk];
            *reinterpret_cast<ulonglong2*>(
                out + (size_t)(tokbase + tb * 8 + tk) * OUT_CH + obase + o4) = o;
        }
    }
}

extern "C" void kernel_launch(void* const* d_in, const int* in_sizes, int n_in,
                              void* d_out, int out_size) {
    (void)in_sizes; (void)n_in; (void)out_size;
    const float* x    = (const float*)d_in[0];   // [8192, 4096]
    const float* Lm   = (const float*)d_in[1];   // [4096, 16]
    const float* Rm   = (const float*)d_in[2];   // [16, 4096]
    const float* bias = (const float*)d_in[3];   // [4096]
    float* out = (float*)d_out;                  // [8192, 4096]

    k1_xRt<<<N_TOKENS / 32, 256>>>(x, Rm);
    k2_tLt<<<(N_TOKENS / 32) * (OUT_CH / 512), 128>>>(Lm, bias, out);
}